// round 2
// baseline (speedup 1.0000x reference)
#include <cuda_runtime.h>

#define NHEAD  8
#define HDIM   32
#define CD     256
#define NTOK   49
#define BWIN   1024
#define MROWS  50176

__device__ float g_q[BWIN * NHEAD * NTOK * HDIM];
__device__ float g_k[BWIN * NHEAD * NTOK * HDIM];
__device__ float g_v[BWIN * NHEAD * NTOK * HDIM];
__device__ float g_ao[MROWS * CD];

__device__ __forceinline__ unsigned f2tf(float f) {
    unsigned u;
    asm("cvt.rna.tf32.f32 %0, %1;" : "=r"(u) : "f"(f));
    return u;
}

__device__ __forceinline__ void mma8(float* c, const unsigned* a, const unsigned* b) {
    asm volatile(
        "mma.sync.aligned.m16n8k8.row.col.f32.tf32.tf32.f32 "
        "{%0,%1,%2,%3},{%4,%5,%6,%7},{%8,%9},{%0,%1,%2,%3};"
        : "+f"(c[0]), "+f"(c[1]), "+f"(c[2]), "+f"(c[3])
        : "r"(a[0]), "r"(a[1]), "r"(a[2]), "r"(a[3]), "r"(b[0]), "r"(b[1]));
}

// ============================================================
// Kernel 1: QKV GEMM (M=50176, N=768, K=256), gather fused,
// double-buffered (LDG->reg overlap with MMA compute).
// ============================================================
__global__ void __launch_bounds__(128) qkv_gemm(
    const float* __restrict__ Q, const float* __restrict__ Wq,
    const float* __restrict__ Bq)
{
    __shared__ unsigned As[2][64][36];
    __shared__ unsigned Bs[2][32][68];
    __shared__ int rsrc[64];

    const int tid = threadIdx.x;
    const int m0 = blockIdx.x * 64;
    const int n0 = blockIdx.y * 64;

    if (tid < 64) {
        int m = m0 + tid;
        int win = m / 49, n = m - win * 49;
        int b = win >> 6, wy = (win >> 3) & 7, wx = win & 7;
        int iy = n / 7, ix = n - iy * 7;
        int y = wy * 7 + iy + 3; if (y >= 56) y -= 56;
        int x = wx * 7 + ix + 3; if (x >= 56) x -= 56;
        rsrc[tid] = ((b * 56 + y) * 56 + x) * 256;
    }
    __syncthreads();

    float acc[2][4][4];
#pragma unroll
    for (int i = 0; i < 2; i++)
#pragma unroll
        for (int j = 0; j < 4; j++)
#pragma unroll
            for (int l = 0; l < 4; l++) acc[i][j][l] = 0.f;

    const int warp = tid >> 5, lane = tid & 31;
    const int g = lane >> 2, tg = lane & 3;
    const int wm = warp >> 1, wn = warp & 1;

    float4 pa[4], pb[4];

#define LDG_AB(K0)                                                          \
    {                                                                       \
        _Pragma("unroll") for (int t = 0; t < 4; t++) {                     \
            int idx = tid + t * 128;                                        \
            int r = idx >> 3, c = (idx & 7) << 2;                           \
            pa[t] = *(const float4*)(Q + rsrc[r] + (K0) + c);               \
        }                                                                   \
        _Pragma("unroll") for (int t = 0; t < 4; t++) {                     \
            int idx = tid + t * 128;                                        \
            int kk = idx >> 4, c = (idx & 15) << 2;                         \
            pb[t] = *(const float4*)(Wq + ((K0) + kk) * 768 + n0 + c);      \
        }                                                                   \
    }

#define STS_AB(BUF)                                                         \
    {                                                                       \
        _Pragma("unroll") for (int t = 0; t < 4; t++) {                     \
            int idx = tid + t * 128;                                        \
            int r = idx >> 3, c = (idx & 7) << 2;                           \
            *(uint4*)&As[BUF][r][c] =                                       \
                make_uint4(f2tf(pa[t].x), f2tf(pa[t].y),                    \
                           f2tf(pa[t].z), f2tf(pa[t].w));                   \
        }                                                                   \
        _Pragma("unroll") for (int t = 0; t < 4; t++) {                     \
            int idx = tid + t * 128;                                        \
            int kk = idx >> 4, c = (idx & 15) << 2;                         \
            *(uint4*)&Bs[BUF][kk][c] =                                      \
                make_uint4(f2tf(pb[t].x), f2tf(pb[t].y),                    \
                           f2tf(pb[t].z), f2tf(pb[t].w));                   \
        }                                                                   \
    }

    LDG_AB(0);
    STS_AB(0);
    __syncthreads();

    int buf = 0;
    for (int it = 0; it < 8; it++) {
        if (it < 7) LDG_AB(32 * (it + 1));

#pragma unroll
        for (int ka = 0; ka < 4; ka++) {
            unsigned a[2][4], bb[4][2];
#pragma unroll
            for (int ma = 0; ma < 2; ma++) {
                int r = wm * 32 + ma * 16 + g;
                a[ma][0] = As[buf][r][ka * 8 + tg];
                a[ma][1] = As[buf][r + 8][ka * 8 + tg];
                a[ma][2] = As[buf][r][ka * 8 + tg + 4];
                a[ma][3] = As[buf][r + 8][ka * 8 + tg + 4];
            }
#pragma unroll
            for (int na = 0; na < 4; na++) {
                int c = wn * 32 + na * 8 + g;
                bb[na][0] = Bs[buf][ka * 8 + tg][c];
                bb[na][1] = Bs[buf][ka * 8 + tg + 4][c];
            }
#pragma unroll
            for (int ma = 0; ma < 2; ma++)
#pragma unroll
                for (int na = 0; na < 4; na++) mma8(acc[ma][na], a[ma], bb[na]);
        }

        if (it < 7) STS_AB(buf ^ 1);
        __syncthreads();
        buf ^= 1;
    }
#undef LDG_AB
#undef STS_AB

    const float scale = 0.17677669529663687f;
#pragma unroll
    for (int ma = 0; ma < 2; ma++) {
#pragma unroll
        for (int rr = 0; rr < 2; rr++) {
            int r = m0 + wm * 32 + ma * 16 + g + rr * 8;
            int win = r / 49, n = r - win * 49;
#pragma unroll
            for (int na = 0; na < 4; na++) {
                int c = n0 + wn * 32 + na * 8 + tg * 2;
                float v0 = acc[ma][na][rr * 2 + 0] + Bq[c];
                float v1 = acc[ma][na][rr * 2 + 1] + Bq[c + 1];
                int part = c >> 8;
                if (part == 0) { v0 *= scale; v1 *= scale; }
                int hh = (c >> 5) & 7, d = c & 31;
                float* dst = (part == 0) ? g_q : ((part == 1) ? g_k : g_v);
                *(float2*)(dst + (((win << 3) + hh) * 49 + n) * 32 + d) =
                    make_float2(v0, v1);
            }
        }
    }
}

// ============================================================
// Kernel 2: tensor-core windowed attention.
// Block = (window, head), 128 threads (4 warps), each warp owns
// a 16-row M tile. S = QK^T (M=64,N=56,K=32), softmax, PV
// (M=64,N=32,K=56), normalization folded into the epilogue.
// ============================================================
__global__ void __launch_bounds__(128) attn_kernel(const float* __restrict__ rbt)
{
    const int bx = blockIdx.x;
    const int win = bx >> 3, h = bx & 7;

    __shared__ unsigned As[64][36];      // Q tf32, rows 49-63 garbage (discarded)
    __shared__ unsigned Kt[32][57];      // K^T tf32 [d][token]
    __shared__ unsigned Vs[56][36];      // V tf32, rows 49-55 zeroed
    __shared__ float    S[64][57];       // scores -> P (tf32-bit floats)
    __shared__ float    biasH[169];
    __shared__ float    inv[49];
    __shared__ int      cnt[49];

    const int tid = threadIdx.x;
    const int warp = tid >> 5, lane = tid & 31;
    const int g = lane >> 2, tg = lane & 3;

    const int base = ((win * 8 + h) * 49) * 32;
    const float* qp = g_q + base;
    const float* kp = g_k + base;
    const float* vp = g_v + base;

    for (int i = tid; i < 392; i += 128) {              // Q
        float4 v = ((const float4*)qp)[i];
        int r = i >> 3, c = (i & 7) << 2;
        As[r][c + 0] = f2tf(v.x); As[r][c + 1] = f2tf(v.y);
        As[r][c + 2] = f2tf(v.z); As[r][c + 3] = f2tf(v.w);
    }
    for (int i = tid; i < 1568; i += 128) {             // K transposed
        int n = i >> 5, d = i & 31;
        Kt[d][n] = f2tf(kp[i]);
    }
    for (int i = tid; i < 1792; i += 128) {             // V (+zero pad rows)
        int n = i >> 5, d = i & 31;
        Vs[n][d] = (i < 1568) ? f2tf(vp[i]) : 0u;
    }
    for (int i = tid; i < 169; i += 128) biasH[i] = rbt[i * 8 + h];
    if (tid < 49) {
        int iy = tid / 7, ix = tid - iy * 7;
        int wy = (win >> 3) & 7, wx = win & 7;
        int y = wy * 7 + iy, x = wx * 7 + ix;
        int ry = y < 49 ? 0 : (y < 53 ? 1 : 2);
        int rx = x < 49 ? 0 : (x < 53 ? 1 : 2);
        cnt[tid] = ry * 3 + rx;
    }
    __syncthreads();

    // ---- S = Q K^T ----
    const int r0 = warp * 16 + g;
    {
        float acc[7][4];
#pragma unroll
        for (int na = 0; na < 7; na++)
#pragma unroll
            for (int l = 0; l < 4; l++) acc[na][l] = 0.f;

#pragma unroll
        for (int ka = 0; ka < 4; ka++) {
            unsigned a[4];
            a[0] = As[r0][ka * 8 + tg];
            a[1] = As[r0 + 8][ka * 8 + tg];
            a[2] = As[r0][ka * 8 + tg + 4];
            a[3] = As[r0 + 8][ka * 8 + tg + 4];
#pragma unroll
            for (int na = 0; na < 7; na++) {
                unsigned b[2] = { Kt[ka * 8 + tg][na * 8 + g],
                                  Kt[ka * 8 + tg + 4][na * 8 + g] };
                mma8(acc[na], a, b);
            }
        }

        // epilogue: bias + shift mask, padding handled explicitly
#pragma unroll
        for (int half = 0; half < 2; half++) {
            int row = r0 + half * 8;
            bool rok = row < 49;
            int iy = 0, ix = 0, ci = 0;
            if (rok) { iy = row / 7; ix = row - iy * 7; ci = cnt[row]; }
#pragma unroll
            for (int na = 0; na < 7; na++) {
#pragma unroll
                for (int e = 0; e < 2; e++) {
                    int col = na * 8 + 2 * tg + e;
                    float v;
                    if (!rok) v = 0.f;
                    else if (col >= 49) v = -1e30f;
                    else {
                        int jy = col / 7, jx = col - jy * 7;
                        v = acc[na][half * 2 + e]
                          + biasH[(iy - jy + 6) * 13 + (ix - jx + 6)];
                        if (cnt[col] != ci) v -= 100.f;
                    }
                    S[row][col] = v;
                }
            }
        }
    }
    __syncthreads();

    // ---- softmax (unnormalized; 1/sum saved for epilogue) ----
    if (tid < 49) {
        const int i = tid;
        float mx = -1e30f;
        for (int j = 0; j < 49; j++) mx = fmaxf(mx, S[i][j]);
        float sum = 0.f;
        for (int j = 0; j < 49; j++) {
            float e = __expf(S[i][j] - mx);
            sum += e;
            S[i][j] = __uint_as_float(f2tf(e));
        }
        for (int j = 49; j < 56; j++) S[i][j] = 0.f;
        inv[i] = 1.f / sum;
    }
    __syncthreads();

    // ---- O = P V ----
    {
        float o[4][4];
#pragma unroll
        for (int na = 0; na < 4; na++)
#pragma unroll
            for (int l = 0; l < 4; l++) o[na][l] = 0.f;

#pragma unroll
        for (int ka = 0; ka < 7; ka++) {
            unsigned a[4];
            a[0] = __float_as_uint(S[r0][ka * 8 + tg]);
            a[1] = __float_as_uint(S[r0 + 8][ka * 8 + tg]);
            a[2] = __float_as_uint(S[r0][ka * 8 + tg + 4]);
            a[3] = __float_as_uint(S[r0 + 8][ka * 8 + tg + 4]);
#pragma unroll
            for (int na = 0; na < 4; na++) {
                unsigned b[2] = { Vs[ka * 8 + tg][na * 8 + g],
                                  Vs[ka * 8 + tg + 4][na * 8 + g] };
                mma8(o[na], a, b);
            }
        }

#pragma unroll
        for (int half = 0; half < 2; half++) {
            int row = r0 + half * 8;
            if (row < 49) {
                float s = inv[row];
                float* op = g_ao + (win * 49 + row) * 256 + h * 32;
#pragma unroll
                for (int na = 0; na < 4; na++) {
                    int col = na * 8 + 2 * tg;
                    *(float2*)(op + col) =
                        make_float2(o[na][half * 2 + 0] * s,
                                    o[na][half * 2 + 1] * s);
                }
            }
        }
    }
}

// ============================================================
// Kernel 3: proj GEMM (M=50176, N=256, K=256), double-buffered,
// window-reverse + roll-back scatter fused in epilogue.
// ============================================================
__global__ void __launch_bounds__(128) proj_gemm(
    const float* __restrict__ Wp, const float* __restrict__ Bp,
    float* __restrict__ out)
{
    __shared__ unsigned As[2][64][36];
    __shared__ unsigned Bs[2][32][68];

    const int tid = threadIdx.x;
    const int m0 = blockIdx.x * 64;
    const int n0 = blockIdx.y * 64;

    float acc[2][4][4];
#pragma unroll
    for (int i = 0; i < 2; i++)
#pragma unroll
        for (int j = 0; j < 4; j++)
#pragma unroll
            for (int l = 0; l < 4; l++) acc[i][j][l] = 0.f;

    const int warp = tid >> 5, lane = tid & 31;
    const int g = lane >> 2, tg = lane & 3;
    const int wm = warp >> 1, wn = warp & 1;

    float4 pa[4], pb[4];

#define LDG_AB(K0)                                                          \
    {                                                                       \
        _Pragma("unroll") for (int t = 0; t < 4; t++) {                     \
            int idx = tid + t * 128;                                        \
            int r = idx >> 3, c = (idx & 7) << 2;                           \
            pa[t] = *(const float4*)(g_ao + (m0 + r) * 256 + (K0) + c);     \
        }                                                                   \
        _Pragma("unroll") for (int t = 0; t < 4; t++) {                     \
            int idx = tid + t * 128;                                        \
            int kk = idx >> 4, c = (idx & 15) << 2;                         \
            pb[t] = *(const float4*)(Wp + ((K0) + kk) * 256 + n0 + c);      \
        }                                                                   \
    }

#define STS_AB(BUF)                                                         \
    {                                                                       \
        _Pragma("unroll") for (int t = 0; t < 4; t++) {                     \
            int idx = tid + t * 128;                                        \
            int r = idx >> 3, c = (idx & 7) << 2;                           \
            *(uint4*)&As[BUF][r][c] =                                       \
                make_uint4(f2tf(pa[t].x), f2tf(pa[t].y),                    \
                           f2tf(pa[t].z), f2tf(pa[t].w));                   \
        }                                                                   \
        _Pragma("unroll") for (int t = 0; t < 4; t++) {                     \
            int idx = tid + t * 128;                                        \
            int kk = idx >> 4, c = (idx & 15) << 2;                         \
            *(uint4*)&Bs[BUF][kk][c] =                                      \
                make_uint4(f2tf(pb[t].x), f2tf(pb[t].y),                    \
                           f2tf(pb[t].z), f2tf(pb[t].w));                   \
        }                                                                   \
    }

    LDG_AB(0);
    STS_AB(0);
    __syncthreads();

    int buf = 0;
    for (int it = 0; it < 8; it++) {
        if (it < 7) LDG_AB(32 * (it + 1));

#pragma unroll
        for (int ka = 0; ka < 4; ka++) {
            unsigned a[2][4], bb[4][2];
#pragma unroll
            for (int ma = 0; ma < 2; ma++) {
                int r = wm * 32 + ma * 16 + g;
                a[ma][0] = As[buf][r][ka * 8 + tg];
                a[ma][1] = As[buf][r + 8][ka * 8 + tg];
                a[ma][2] = As[buf][r][ka * 8 + tg + 4];
                a[ma][3] = As[buf][r + 8][ka * 8 + tg + 4];
            }
#pragma unroll
            for (int na = 0; na < 4; na++) {
                int c = wn * 32 + na * 8 + g;
                bb[na][0] = Bs[buf][ka * 8 + tg][c];
                bb[na][1] = Bs[buf][ka * 8 + tg + 4][c];
            }
#pragma unroll
            for (int ma = 0; ma < 2; ma++)
#pragma unroll
                for (int na = 0; na < 4; na++) mma8(acc[ma][na], a[ma], bb[na]);
        }

        if (it < 7) STS_AB(buf ^ 1);
        __syncthreads();
        buf ^= 1;
    }
#undef LDG_AB
#undef STS_AB

#pragma unroll
    for (int ma = 0; ma < 2; ma++) {
#pragma unroll
        for (int rr = 0; rr < 2; rr++) {
            int r = m0 + wm * 32 + ma * 16 + g + rr * 8;
            int win = r / 49, n = r - win * 49;
            int b = win >> 6, wy = (win >> 3) & 7, wx = win & 7;
            int iy = n / 7, ix = n - iy * 7;
            int y = wy * 7 + iy + 3; if (y >= 56) y -= 56;
            int x = wx * 7 + ix + 3; if (x >= 56) x -= 56;
            int obase = ((b * 56 + y) * 56 + x) * 256;
#pragma unroll
            for (int na = 0; na < 4; na++) {
                int c = n0 + wn * 32 + na * 8 + tg * 2;
                float v0 = acc[ma][na][rr * 2 + 0] + Bp[c];
                float v1 = acc[ma][na][rr * 2 + 1] + Bp[c + 1];
                *(float2*)(out + obase + c) = make_float2(v0, v1);
            }
        }
    }
}

// ============================================================
extern "C" void kernel_launch(void* const* d_in, const int* in_sizes, int n_in,
                              void* d_out, int out_size)
{
    const float* query  = (const float*)d_in[0];
    const float* w_qkv  = (const float*)d_in[1];
    const float* b_qkv  = (const float*)d_in[2];
    const float* w_proj = (const float*)d_in[3];
    const float* b_proj = (const float*)d_in[4];
    const float* rbt    = (const float*)d_in[5];
    float* out = (float*)d_out;

    dim3 g1(784, 12);
    qkv_gemm<<<g1, 128>>>(query, w_qkv, b_qkv);

    attn_kernel<<<8192, 128>>>(rbt);

    dim3 g3(784, 4);
    proj_gemm<<<g3, 128>>>(w_proj, b_proj, out);
}

// round 3
// speedup vs baseline: 1.1004x; 1.1004x over previous
#include <cuda_runtime.h>

#define NHEAD  8
#define HDIM   32
#define CD     256
#define NTOK   49
#define BWIN   1024
#define MROWS  50176
#define NQ     12845056           // 16*56*56*256 == MROWS*CD
#define NW1    196608             // 256*768
#define NW2    65536              // 256*256

__device__ float g_q[BWIN * NHEAD * NTOK * HDIM];
__device__ float g_k[BWIN * NHEAD * NTOK * HDIM];
__device__ float g_v[BWIN * NHEAD * NTOK * HDIM];
__device__ float g_ao[MROWS * CD];          // (1) rounded query, (2) attn out
__device__ float g_wqkv[NW1];
__device__ float g_wproj[NW2];

__device__ __forceinline__ unsigned f2tf(float f) {
    unsigned u;
    asm("cvt.rna.tf32.f32 %0, %1;" : "=r"(u) : "f"(f));
    return u;
}
__device__ __forceinline__ float rtf(float f) { return __uint_as_float(f2tf(f)); }

__device__ __forceinline__ void mma8(float* c, const unsigned* a, const unsigned* b) {
    asm volatile(
        "mma.sync.aligned.m16n8k8.row.col.f32.tf32.tf32.f32 "
        "{%0,%1,%2,%3},{%4,%5,%6,%7},{%8,%9},{%0,%1,%2,%3};"
        : "+f"(c[0]), "+f"(c[1]), "+f"(c[2]), "+f"(c[3])
        : "r"(a[0]), "r"(a[1]), "r"(a[2]), "r"(a[3]), "r"(b[0]), "r"(b[1]));
}

__device__ __forceinline__ void cpa16(unsigned dst, const void* src) {
    asm volatile("cp.async.cg.shared.global [%0], [%1], 16;" :: "r"(dst), "l"(src));
}
__device__ __forceinline__ void cpa_commit() {
    asm volatile("cp.async.commit_group;");
}
template <int N>
__device__ __forceinline__ void cpa_wait() {
    asm volatile("cp.async.wait_group %0;" :: "n"(N));
}

// ============================================================
// Pre-pass: round query + both weight matrices to TF32 (RNA).
// Rounded query goes to g_ao (free until attn overwrites it).
// ============================================================
__global__ void __launch_bounds__(256) round_pre(
    const float4* __restrict__ q, const float4* __restrict__ w1,
    const float4* __restrict__ w2)
{
    int i = blockIdx.x * 256 + threadIdx.x;
    const int NQ4 = NQ / 4, NW14 = NW1 / 4;
    float4 v; float4* dst;
    if (i < NQ4)              { v = q[i];               dst = (float4*)g_ao + i; }
    else if (i < NQ4 + NW14)  { v = w1[i - NQ4];        dst = (float4*)g_wqkv + (i - NQ4); }
    else                      { v = w2[i - NQ4 - NW14]; dst = (float4*)g_wproj + (i - NQ4 - NW14); }
    *dst = make_float4(rtf(v.x), rtf(v.y), rtf(v.z), rtf(v.w));
}

// ============================================================
// Shared GEMM tile geometry: block 128x128, 8 warps (2m x 4n),
// warp tile 64x32, K-slice 32, 3-stage cp.async pipeline.
// smem (dynamic): A[3][128][36] + B[3][32][136] fp32 = 107520 B
// ============================================================
#define A_ST 4608          // 128*36 floats per stage
#define B_ST 4352          // 32*136 floats per stage
#define B_BASE 13824       // 3*A_ST
#define SMEM_BYTES 107520

// QKV GEMM: M=50176, N=768, K=256. A gathered (roll + window partition).
__global__ void __launch_bounds__(256) qkv_gemm(const float* __restrict__ Bq)
{
    extern __shared__ float sm[];
    __shared__ int rsrc[128];

    const int tid = threadIdx.x;
    const int m0 = blockIdx.x * 128;
    const int n0 = blockIdx.y * 128;

    if (tid < 128) {
        int m = m0 + tid;
        int win = m / 49, n = m - win * 49;
        int b = win >> 6, wy = (win >> 3) & 7, wx = win & 7;
        int iy = n / 7, ix = n - iy * 7;
        int y = wy * 7 + iy + 3; if (y >= 56) y -= 56;
        int x = wx * 7 + ix + 3; if (x >= 56) x -= 56;
        rsrc[tid] = ((b * 56 + y) * 56 + x) * 256;
    }
    __syncthreads();

    const unsigned sbase = (unsigned)__cvta_generic_to_shared(sm);

    // per-thread load assignments (4 chunks A, 4 chunks B per stage)
    int ar[4], ac[4], bk[4], bc[4];
#pragma unroll
    for (int t = 0; t < 4; t++) {
        int id = tid + t * 256;
        ar[t] = id >> 3;  ac[t] = (id & 7) << 2;
        bk[t] = id >> 5;  bc[t] = (id & 31) << 2;
    }

#define ISSUE(STG, K0)                                                        \
    {                                                                         \
        _Pragma("unroll") for (int t = 0; t < 4; t++)                         \
            cpa16(sbase + ((STG) * A_ST + ar[t] * 36 + ac[t]) * 4,            \
                  g_ao + rsrc[ar[t]] + (K0) + ac[t]);                         \
        _Pragma("unroll") for (int t = 0; t < 4; t++)                         \
            cpa16(sbase + (B_BASE + (STG) * B_ST + bk[t] * 136 + bc[t]) * 4,  \
                  g_wqkv + ((K0) + bk[t]) * 768 + n0 + bc[t]);                \
    }

    float acc[4][4][4];
#pragma unroll
    for (int i = 0; i < 4; i++)
#pragma unroll
        for (int j = 0; j < 4; j++)
#pragma unroll
            for (int l = 0; l < 4; l++) acc[i][j][l] = 0.f;

    const int warp = tid >> 5, lane = tid & 31;
    const int g = lane >> 2, tg = lane & 3;
    const int wm = warp >> 2, wn = warp & 3;

    ISSUE(0, 0);  cpa_commit();
    ISSUE(1, 32); cpa_commit();
    cpa_wait<1>();
    __syncthreads();

    for (int it = 0; it < 8; it++) {
        const int stg = it - (it >= 6 ? 6 : (it >= 3 ? 3 : 0));   // it % 3
        const float* As = sm + stg * A_ST;
        const float* Bs = sm + B_BASE + stg * B_ST;

#pragma unroll
        for (int ka = 0; ka < 4; ka++) {
            unsigned a[4][4], bb[4][2];
#pragma unroll
            for (int ma = 0; ma < 4; ma++) {
                int r = wm * 64 + ma * 16 + g;
                a[ma][0] = __float_as_uint(As[r * 36 + ka * 8 + tg]);
                a[ma][1] = __float_as_uint(As[(r + 8) * 36 + ka * 8 + tg]);
                a[ma][2] = __float_as_uint(As[r * 36 + ka * 8 + tg + 4]);
                a[ma][3] = __float_as_uint(As[(r + 8) * 36 + ka * 8 + tg + 4]);
            }
#pragma unroll
            for (int na = 0; na < 4; na++) {
                int c = wn * 32 + na * 8 + g;
                bb[na][0] = __float_as_uint(Bs[(ka * 8 + tg) * 136 + c]);
                bb[na][1] = __float_as_uint(Bs[(ka * 8 + tg + 4) * 136 + c]);
            }
#pragma unroll
            for (int ma = 0; ma < 4; ma++)
#pragma unroll
                for (int na = 0; na < 4; na++) mma8(acc[ma][na], a[ma], bb[na]);
        }

        if (it + 2 < 8) {
            int ns = it + 2; ns -= (ns >= 6 ? 6 : (ns >= 3 ? 3 : 0));
            ISSUE(ns, (it + 2) * 32);
        }
        cpa_commit();
        cpa_wait<1>();
        __syncthreads();
    }
#undef ISSUE

    const float scale = 0.17677669529663687f;
#pragma unroll
    for (int ma = 0; ma < 4; ma++) {
#pragma unroll
        for (int rr = 0; rr < 2; rr++) {
            int r = m0 + wm * 64 + ma * 16 + g + rr * 8;
            int win = r / 49, n = r - win * 49;
#pragma unroll
            for (int na = 0; na < 4; na++) {
                int c = n0 + wn * 32 + na * 8 + tg * 2;
                float v0 = acc[ma][na][rr * 2 + 0] + Bq[c];
                float v1 = acc[ma][na][rr * 2 + 1] + Bq[c + 1];
                int part = c >> 8;
                if (part == 0) { v0 *= scale; v1 *= scale; }
                int hh = (c >> 5) & 7, d = c & 31;
                float* dst = (part == 0) ? g_q : ((part == 1) ? g_k : g_v);
                *(float2*)(dst + (((win << 3) + hh) * 49 + n) * 32 + d) =
                    make_float2(rtf(v0), rtf(v1));      // pre-round for attn MMAs
            }
        }
    }
}

// ============================================================
// Attention: block = (window, head), 128 threads. Inputs are
// pre-rounded TF32 bits -> pure bit copies, no cvt in loads.
// Warp-per-row softmax with shuffle reductions.
// ============================================================
__global__ void __launch_bounds__(128) attn_kernel(const float* __restrict__ rbt)
{
    const int bx = blockIdx.x;
    const int win = bx >> 3, h = bx & 7;

    __shared__ unsigned As[64][36];
    __shared__ unsigned Kt[32][57];
    __shared__ unsigned Vs[56][36];
    __shared__ float    S[64][57];
    __shared__ float    biasH[169];
    __shared__ float    inv[49];
    __shared__ int      cnt[49];

    const int tid = threadIdx.x;
    const int warp = tid >> 5, lane = tid & 31;
    const int g = lane >> 2, tg = lane & 3;

    const int base = ((win * 8 + h) * 49) * 32;
    const float* qp = g_q + base;
    const float* kp = g_k + base;
    const float* vp = g_v + base;

    for (int i = tid; i < 392; i += 128) {
        int r = i >> 3, c = (i & 7) << 2;
        *(uint4*)&As[r][c] = ((const uint4*)qp)[i];
    }
    for (int i = tid; i < 1568; i += 128) {
        int n = i >> 5, d = i & 31;
        Kt[d][n] = __float_as_uint(kp[i]);
    }
    for (int i = tid; i < 1792; i += 128) {
        int n = i >> 5, d = i & 31;
        Vs[n][d] = (i < 1568) ? __float_as_uint(vp[i]) : 0u;
    }
    for (int i = tid; i < 169; i += 128) biasH[i] = rbt[i * 8 + h];
    if (tid < 49) {
        int iy = tid / 7, ix = tid - iy * 7;
        int wy = (win >> 3) & 7, wx = win & 7;
        int y = wy * 7 + iy, x = wx * 7 + ix;
        int ry = y < 49 ? 0 : (y < 53 ? 1 : 2);
        int rx = x < 49 ? 0 : (x < 53 ? 1 : 2);
        cnt[tid] = ry * 3 + rx;
    }
    __syncthreads();

    // ---- S = Q K^T ----
    const int r0 = warp * 16 + g;
    {
        float acc[7][4];
#pragma unroll
        for (int na = 0; na < 7; na++)
#pragma unroll
            for (int l = 0; l < 4; l++) acc[na][l] = 0.f;

#pragma unroll
        for (int ka = 0; ka < 4; ka++) {
            unsigned a[4];
            a[0] = As[r0][ka * 8 + tg];
            a[1] = As[r0 + 8][ka * 8 + tg];
            a[2] = As[r0][ka * 8 + tg + 4];
            a[3] = As[r0 + 8][ka * 8 + tg + 4];
#pragma unroll
            for (int na = 0; na < 7; na++) {
                unsigned b[2] = { Kt[ka * 8 + tg][na * 8 + g],
                                  Kt[ka * 8 + tg + 4][na * 8 + g] };
                mma8(acc[na], a, b);
            }
        }

#pragma unroll
        for (int half = 0; half < 2; half++) {
            int row = r0 + half * 8;
            bool rok = row < 49;
            int iy = 0, ix = 0, ci = 0;
            if (rok) { iy = row / 7; ix = row - iy * 7; ci = cnt[row]; }
#pragma unroll
            for (int na = 0; na < 7; na++) {
#pragma unroll
                for (int e = 0; e < 2; e++) {
                    int col = na * 8 + 2 * tg + e;
                    float v;
                    if (!rok) v = 0.f;
                    else if (col >= 49) v = -1e30f;
                    else {
                        int jy = col / 7, jx = col - jy * 7;
                        v = acc[na][half * 2 + e]
                          + biasH[(iy - jy + 6) * 13 + (ix - jx + 6)];
                        if (cnt[col] != ci) v -= 100.f;
                    }
                    S[row][col] = v;
                }
            }
        }
    }
    __syncthreads();

    // ---- softmax: warp per row, shuffle reductions ----
    for (int row = warp; row < 49; row += 4) {
        float v1 = (lane < 49) ? S[row][lane] : -1e30f;
        float v2 = (lane + 32 < 49) ? S[row][lane + 32] : -1e30f;
        float m = fmaxf(v1, v2);
#pragma unroll
        for (int o = 16; o > 0; o >>= 1)
            m = fmaxf(m, __shfl_xor_sync(0xffffffffu, m, o));
        float e1 = (lane < 49) ? __expf(v1 - m) : 0.f;
        float e2 = (lane + 32 < 49) ? __expf(v2 - m) : 0.f;
        float s = e1 + e2;
#pragma unroll
        for (int o = 16; o > 0; o >>= 1)
            s += __shfl_xor_sync(0xffffffffu, s, o);
        S[row][lane] = __uint_as_float(f2tf(e1));
        if (lane + 32 < 56) S[row][lane + 32] = __uint_as_float(f2tf(e2));
        if (lane == 0) inv[row] = 1.f / s;
    }
    __syncthreads();

    // ---- O = P V ----
    {
        float o[4][4];
#pragma unroll
        for (int na = 0; na < 4; na++)
#pragma unroll
            for (int l = 0; l < 4; l++) o[na][l] = 0.f;

#pragma unroll
        for (int ka = 0; ka < 7; ka++) {
            unsigned a[4];
            a[0] = __float_as_uint(S[r0][ka * 8 + tg]);
            a[1] = __float_as_uint(S[r0 + 8][ka * 8 + tg]);
            a[2] = __float_as_uint(S[r0][ka * 8 + tg + 4]);
            a[3] = __float_as_uint(S[r0 + 8][ka * 8 + tg + 4]);
#pragma unroll
            for (int na = 0; na < 4; na++) {
                unsigned b[2] = { Vs[ka * 8 + tg][na * 8 + g],
                                  Vs[ka * 8 + tg + 4][na * 8 + g] };
                mma8(o[na], a, b);
            }
        }

#pragma unroll
        for (int half = 0; half < 2; half++) {
            int row = r0 + half * 8;
            if (row < 49) {
                float s = inv[row];
                float* op = g_ao + (win * 49 + row) * 256 + h * 32;
#pragma unroll
                for (int na = 0; na < 4; na++) {
                    int col = na * 8 + 2 * tg;
                    *(float2*)(op + col) =
                        make_float2(rtf(o[na][half * 2 + 0] * s),
                                    rtf(o[na][half * 2 + 1] * s));
                }
            }
        }
    }
}

// ============================================================
// Proj GEMM: M=50176, N=256, K=256, same pipeline; fused
// window-reverse + roll-back scatter epilogue.
// ============================================================
__global__ void __launch_bounds__(256) proj_gemm(
    const float* __restrict__ Bp, float* __restrict__ out)
{
    extern __shared__ float sm[];

    const int tid = threadIdx.x;
    const int m0 = blockIdx.x * 128;
    const int n0 = blockIdx.y * 128;

    const unsigned sbase = (unsigned)__cvta_generic_to_shared(sm);

    int ar[4], ac[4], bk[4], bc[4];
#pragma unroll
    for (int t = 0; t < 4; t++) {
        int id = tid + t * 256;
        ar[t] = id >> 3;  ac[t] = (id & 7) << 2;
        bk[t] = id >> 5;  bc[t] = (id & 31) << 2;
    }

#define ISSUE(STG, K0)                                                        \
    {                                                                         \
        _Pragma("unroll") for (int t = 0; t < 4; t++)                         \
            cpa16(sbase + ((STG) * A_ST + ar[t] * 36 + ac[t]) * 4,            \
                  g_ao + (m0 + ar[t]) * 256 + (K0) + ac[t]);                  \
        _Pragma("unroll") for (int t = 0; t < 4; t++)                         \
            cpa16(sbase + (B_BASE + (STG) * B_ST + bk[t] * 136 + bc[t]) * 4,  \
                  g_wproj + ((K0) + bk[t]) * 256 + n0 + bc[t]);               \
    }

    float acc[4][4][4];
#pragma unroll
    for (int i = 0; i < 4; i++)
#pragma unroll
        for (int j = 0; j < 4; j++)
#pragma unroll
            for (int l = 0; l < 4; l++) acc[i][j][l] = 0.f;

    const int warp = tid >> 5, lane = tid & 31;
    const int g = lane >> 2, tg = lane & 3;
    const int wm = warp >> 2, wn = warp & 3;

    ISSUE(0, 0);  cpa_commit();
    ISSUE(1, 32); cpa_commit();
    cpa_wait<1>();
    __syncthreads();

    for (int it = 0; it < 8; it++) {
        const int stg = it - (it >= 6 ? 6 : (it >= 3 ? 3 : 0));
        const float* As = sm + stg * A_ST;
        const float* Bs = sm + B_BASE + stg * B_ST;

#pragma unroll
        for (int ka = 0; ka < 4; ka++) {
            unsigned a[4][4], bb[4][2];
#pragma unroll
            for (int ma = 0; ma < 4; ma++) {
                int r = wm * 64 + ma * 16 + g;
                a[ma][0] = __float_as_uint(As[r * 36 + ka * 8 + tg]);
                a[ma][1] = __float_as_uint(As[(r + 8) * 36 + ka * 8 + tg]);
                a[ma][2] = __float_as_uint(As[r * 36 + ka * 8 + tg + 4]);
                a[ma][3] = __float_as_uint(As[(r + 8) * 36 + ka * 8 + tg + 4]);
            }
#pragma unroll
            for (int na = 0; na < 4; na++) {
                int c = wn * 32 + na * 8 + g;
                bb[na][0] = __float_as_uint(Bs[(ka * 8 + tg) * 136 + c]);
                bb[na][1] = __float_as_uint(Bs[(ka * 8 + tg + 4) * 136 + c]);
            }
#pragma unroll
            for (int ma = 0; ma < 4; ma++)
#pragma unroll
                for (int na = 0; na < 4; na++) mma8(acc[ma][na], a[ma], bb[na]);
        }

        if (it + 2 < 8) {
            int ns = it + 2; ns -= (ns >= 6 ? 6 : (ns >= 3 ? 3 : 0));
            ISSUE(ns, (it + 2) * 32);
        }
        cpa_commit();
        cpa_wait<1>();
        __syncthreads();
    }
#undef ISSUE

#pragma unroll
    for (int ma = 0; ma < 4; ma++) {
#pragma unroll
        for (int rr = 0; rr < 2; rr++) {
            int r = m0 + wm * 64 + ma * 16 + g + rr * 8;
            int win = r / 49, n = r - win * 49;
            int b = win >> 6, wy = (win >> 3) & 7, wx = win & 7;
            int iy = n / 7, ix = n - iy * 7;
            int y = wy * 7 + iy + 3; if (y >= 56) y -= 56;
            int x = wx * 7 + ix + 3; if (x >= 56) x -= 56;
            int obase = ((b * 56 + y) * 56 + x) * 256;
#pragma unroll
            for (int na = 0; na < 4; na++) {
                int c = n0 + wn * 32 + na * 8 + tg * 2;
                float v0 = acc[ma][na][rr * 2 + 0] + Bp[c];
                float v1 = acc[ma][na][rr * 2 + 1] + Bp[c + 1];
                *(float2*)(out + obase + c) = make_float2(v0, v1);
            }
        }
    }
}

// ============================================================
extern "C" void kernel_launch(void* const* d_in, const int* in_sizes, int n_in,
                              void* d_out, int out_size)
{
    const float* query  = (const float*)d_in[0];
    const float* w_qkv  = (const float*)d_in[1];
    const float* b_qkv  = (const float*)d_in[2];
    const float* w_proj = (const float*)d_in[3];
    const float* b_proj = (const float*)d_in[4];
    const float* rbt    = (const float*)d_in[5];
    float* out = (float*)d_out;

    static int attr_done = 0;
    if (!attr_done) {
        cudaFuncSetAttribute(qkv_gemm,
            cudaFuncAttributeMaxDynamicSharedMemorySize, SMEM_BYTES);
        cudaFuncSetAttribute(proj_gemm,
            cudaFuncAttributeMaxDynamicSharedMemorySize, SMEM_BYTES);
        attr_done = 1;
    }

    round_pre<<<12800, 256>>>((const float4*)query, (const float4*)w_qkv,
                              (const float4*)w_proj);

    dim3 g1(392, 6);
    qkv_gemm<<<g1, 256, SMEM_BYTES>>>(b_qkv);

    attn_kernel<<<8192, 128>>>(rbt);

    dim3 g3(392, 2);
    proj_gemm<<<g3, 256, SMEM_BYTES>>>(b_proj, out);
}

// round 4
// speedup vs baseline: 1.2387x; 1.1257x over previous
#include <cuda_runtime.h>

#define NHEAD  8
#define HDIM   32
#define CD     256
#define NTOK   49
#define BWIN   1024
#define MROWS  50176
#define NQ     12845056           // 16*56*56*256 == MROWS*CD
#define NW1    196608             // 256*768
#define NW2    65536              // 256*256

__device__ float g_q[BWIN * NHEAD * NTOK * HDIM];
__device__ float g_k[BWIN * NHEAD * NTOK * HDIM];
__device__ float g_v[BWIN * NHEAD * NTOK * HDIM];
__device__ float g_ao[MROWS * CD];          // (1) rounded query, (2) attn out
__device__ float g_wqkv[NW1];
__device__ float g_wproj[NW2];

__device__ __forceinline__ unsigned f2tf(float f) {
    unsigned u;
    asm("cvt.rna.tf32.f32 %0, %1;" : "=r"(u) : "f"(f));
    return u;
}
__device__ __forceinline__ float rtf(float f) { return __uint_as_float(f2tf(f)); }

__device__ __forceinline__ void mma8(float* c, const unsigned* a, const unsigned* b) {
    asm volatile(
        "mma.sync.aligned.m16n8k8.row.col.f32.tf32.tf32.f32 "
        "{%0,%1,%2,%3},{%4,%5,%6,%7},{%8,%9},{%0,%1,%2,%3};"
        : "+f"(c[0]), "+f"(c[1]), "+f"(c[2]), "+f"(c[3])
        : "r"(a[0]), "r"(a[1]), "r"(a[2]), "r"(a[3]), "r"(b[0]), "r"(b[1]));
}

__device__ __forceinline__ void cpa16(unsigned dst, const void* src) {
    asm volatile("cp.async.cg.shared.global [%0], [%1], 16;" :: "r"(dst), "l"(src));
}
__device__ __forceinline__ void cpa_commit() {
    asm volatile("cp.async.commit_group;");
}
template <int N>
__device__ __forceinline__ void cpa_wait() {
    asm volatile("cp.async.wait_group %0;" :: "n"(N));
}

// ============================================================
// Pre-pass: round query + both weight matrices to TF32 (RNA).
// ============================================================
__global__ void __launch_bounds__(256) round_pre(
    const float4* __restrict__ q, const float4* __restrict__ w1,
    const float4* __restrict__ w2)
{
    int i = blockIdx.x * 256 + threadIdx.x;
    const int NQ4 = NQ / 4, NW14 = NW1 / 4;
    float4 v; float4* dst;
    if (i < NQ4)              { v = q[i];               dst = (float4*)g_ao + i; }
    else if (i < NQ4 + NW14)  { v = w1[i - NQ4];        dst = (float4*)g_wqkv + (i - NQ4); }
    else                      { v = w2[i - NQ4 - NW14]; dst = (float4*)g_wproj + (i - NQ4 - NW14); }
    *dst = make_float4(rtf(v.x), rtf(v.y), rtf(v.z), rtf(v.w));
}

// ============================================================
// GEMM tiles: block 128x128, 8 warps (2m x 4n), warp 64x32,
// K-slice 32, 3-stage cp.async pipeline.
// ============================================================
#define A_ST 4608
#define B_ST 4352
#define B_BASE 13824
#define SMEM_BYTES 107520

__global__ void __launch_bounds__(256) qkv_gemm(const float* __restrict__ Bq)
{
    extern __shared__ float sm[];
    __shared__ int rsrc[128];

    const int tid = threadIdx.x;
    const int m0 = blockIdx.x * 128;
    const int n0 = blockIdx.y * 128;

    if (tid < 128) {
        int m = m0 + tid;
        int win = m / 49, n = m - win * 49;
        int b = win >> 6, wy = (win >> 3) & 7, wx = win & 7;
        int iy = n / 7, ix = n - iy * 7;
        int y = wy * 7 + iy + 3; if (y >= 56) y -= 56;
        int x = wx * 7 + ix + 3; if (x >= 56) x -= 56;
        rsrc[tid] = ((b * 56 + y) * 56 + x) * 256;
    }
    __syncthreads();

    const unsigned sbase = (unsigned)__cvta_generic_to_shared(sm);

    int ar[4], ac[4], bk[4], bc[4];
#pragma unroll
    for (int t = 0; t < 4; t++) {
        int id = tid + t * 256;
        ar[t] = id >> 3;  ac[t] = (id & 7) << 2;
        bk[t] = id >> 5;  bc[t] = (id & 31) << 2;
    }

#define ISSUE(STG, K0)                                                        \
    {                                                                         \
        _Pragma("unroll") for (int t = 0; t < 4; t++)                         \
            cpa16(sbase + ((STG) * A_ST + ar[t] * 36 + ac[t]) * 4,            \
                  g_ao + rsrc[ar[t]] + (K0) + ac[t]);                         \
        _Pragma("unroll") for (int t = 0; t < 4; t++)                         \
            cpa16(sbase + (B_BASE + (STG) * B_ST + bk[t] * 136 + bc[t]) * 4,  \
                  g_wqkv + ((K0) + bk[t]) * 768 + n0 + bc[t]);                \
    }

    float acc[4][4][4];
#pragma unroll
    for (int i = 0; i < 4; i++)
#pragma unroll
        for (int j = 0; j < 4; j++)
#pragma unroll
            for (int l = 0; l < 4; l++) acc[i][j][l] = 0.f;

    const int warp = tid >> 5, lane = tid & 31;
    const int g = lane >> 2, tg = lane & 3;
    const int wm = warp >> 2, wn = warp & 3;

    ISSUE(0, 0);  cpa_commit();
    ISSUE(1, 32); cpa_commit();
    cpa_wait<1>();
    __syncthreads();

    for (int it = 0; it < 8; it++) {
        const int stg = it - (it >= 6 ? 6 : (it >= 3 ? 3 : 0));
        const float* As = sm + stg * A_ST;
        const float* Bs = sm + B_BASE + stg * B_ST;

#pragma unroll
        for (int ka = 0; ka < 4; ka++) {
            unsigned a[4][4], bb[4][2];
#pragma unroll
            for (int ma = 0; ma < 4; ma++) {
                int r = wm * 64 + ma * 16 + g;
                a[ma][0] = __float_as_uint(As[r * 36 + ka * 8 + tg]);
                a[ma][1] = __float_as_uint(As[(r + 8) * 36 + ka * 8 + tg]);
                a[ma][2] = __float_as_uint(As[r * 36 + ka * 8 + tg + 4]);
                a[ma][3] = __float_as_uint(As[(r + 8) * 36 + ka * 8 + tg + 4]);
            }
#pragma unroll
            for (int na = 0; na < 4; na++) {
                int c = wn * 32 + na * 8 + g;
                bb[na][0] = __float_as_uint(Bs[(ka * 8 + tg) * 136 + c]);
                bb[na][1] = __float_as_uint(Bs[(ka * 8 + tg + 4) * 136 + c]);
            }
#pragma unroll
            for (int ma = 0; ma < 4; ma++)
#pragma unroll
                for (int na = 0; na < 4; na++) mma8(acc[ma][na], a[ma], bb[na]);
        }

        if (it + 2 < 8) {
            int ns = it + 2; ns -= (ns >= 6 ? 6 : (ns >= 3 ? 3 : 0));
            ISSUE(ns, (it + 2) * 32);
        }
        cpa_commit();
        cpa_wait<1>();
        __syncthreads();
    }
#undef ISSUE

    const float scale = 0.17677669529663687f;
#pragma unroll
    for (int ma = 0; ma < 4; ma++) {
#pragma unroll
        for (int rr = 0; rr < 2; rr++) {
            int r = m0 + wm * 64 + ma * 16 + g + rr * 8;
            int win = r / 49, n = r - win * 49;
#pragma unroll
            for (int na = 0; na < 4; na++) {
                int c = n0 + wn * 32 + na * 8 + tg * 2;
                float v0 = acc[ma][na][rr * 2 + 0] + Bq[c];
                float v1 = acc[ma][na][rr * 2 + 1] + Bq[c + 1];
                int part = c >> 8;
                if (part == 0) { v0 *= scale; v1 *= scale; }
                int hh = (c >> 5) & 7, d = c & 31;
                float* dst = (part == 0) ? g_q : ((part == 1) ? g_k : g_v);
                *(float2*)(dst + (((win << 3) + hh) * 49 + n) * 32 + d) =
                    make_float2(rtf(v0), rtf(v1));
            }
        }
    }
}

// ============================================================
// Attention: block = (window, head), 128 threads.
// Softmax fused into the S-MMA epilogue: no max pass (scores are
// small; masked -100 underflows), exp on registers, quad-shuffle
// row sums kept in registers. Single block-wide sync.
// ============================================================
__global__ void __launch_bounds__(128) attn_kernel(const float* __restrict__ rbt)
{
    const int bx = blockIdx.x;
    const int win = bx >> 3, h = bx & 7;

    __shared__ unsigned As[64][36];
    __shared__ unsigned Kt[32][57];
    __shared__ unsigned Vs[56][36];
    __shared__ float    S[64][57];
    __shared__ float    biasH[169];
    __shared__ int      cnt[49];

    const int tid = threadIdx.x;
    const int warp = tid >> 5, lane = tid & 31;
    const int g = lane >> 2, tg = lane & 3;

    const int base = ((win * 8 + h) * 49) * 32;
    const float* qp = g_q + base;
    const float* kp = g_k + base;
    const float* vp = g_v + base;

    for (int i = tid; i < 392; i += 128) {
        int r = i >> 3, c = (i & 7) << 2;
        *(uint4*)&As[r][c] = ((const uint4*)qp)[i];
    }
    for (int i = tid; i < 1568; i += 128) {
        int n = i >> 5, d = i & 31;
        Kt[d][n] = __float_as_uint(kp[i]);
    }
    for (int i = tid; i < 1792; i += 128) {
        int n = i >> 5, d = i & 31;
        Vs[n][d] = (i < 1568) ? __float_as_uint(vp[i]) : 0u;
    }
    for (int i = tid; i < 169; i += 128) biasH[i] = rbt[i * 8 + h];
    if (tid < 49) {
        int iy = tid / 7, ix = tid - iy * 7;
        int wy = (win >> 3) & 7, wx = win & 7;
        int y = wy * 7 + iy, x = wx * 7 + ix;
        int ry = y < 49 ? 0 : (y < 53 ? 1 : 2);
        int rx = x < 49 ? 0 : (x < 53 ? 1 : 2);
        cnt[tid] = ry * 3 + rx;
    }
    __syncthreads();

    // ---- S = Q K^T with fused bias+mask+exp+rowsum ----
    const int r0 = warp * 16 + g;
    float invs[2];
    {
        float acc[7][4];
#pragma unroll
        for (int na = 0; na < 7; na++)
#pragma unroll
            for (int l = 0; l < 4; l++) acc[na][l] = 0.f;

#pragma unroll
        for (int ka = 0; ka < 4; ka++) {
            unsigned a[4];
            a[0] = As[r0][ka * 8 + tg];
            a[1] = As[r0 + 8][ka * 8 + tg];
            a[2] = As[r0][ka * 8 + tg + 4];
            a[3] = As[r0 + 8][ka * 8 + tg + 4];
#pragma unroll
            for (int na = 0; na < 7; na++) {
                unsigned b[2] = { Kt[ka * 8 + tg][na * 8 + g],
                                  Kt[ka * 8 + tg + 4][na * 8 + g] };
                mma8(acc[na], a, b);
            }
        }

#pragma unroll
        for (int half = 0; half < 2; half++) {
            int row = r0 + half * 8;
            bool rok = row < 49;
            int iy = 0, ix = 0, ci = 0;
            if (rok) { iy = row / 7; ix = row - iy * 7; ci = cnt[row]; }
            float esum = 0.f;
#pragma unroll
            for (int na = 0; na < 7; na++) {
#pragma unroll
                for (int e = 0; e < 2; e++) {
                    int col = na * 8 + 2 * tg + e;
                    float ev = 0.f;
                    if (rok && col < 49) {
                        int jy = col / 7, jx = col - jy * 7;
                        float v = acc[na][half * 2 + e]
                                + biasH[(iy - jy + 6) * 13 + (ix - jx + 6)];
                        if (cnt[col] != ci) v -= 100.f;
                        ev = __expf(v);
                    }
                    S[row][col] = __uint_as_float(f2tf(ev));
                    esum += ev;
                }
            }
            esum += __shfl_xor_sync(0xffffffffu, esum, 1);
            esum += __shfl_xor_sync(0xffffffffu, esum, 2);
            invs[half] = 1.f / esum;
        }
    }
    __syncwarp();   // each warp produces and consumes its own 16 S-rows

    // ---- O = P V ----
    {
        float o[4][4];
#pragma unroll
        for (int na = 0; na < 4; na++)
#pragma unroll
            for (int l = 0; l < 4; l++) o[na][l] = 0.f;

#pragma unroll
        for (int ka = 0; ka < 7; ka++) {
            unsigned a[4];
            a[0] = __float_as_uint(S[r0][ka * 8 + tg]);
            a[1] = __float_as_uint(S[r0 + 8][ka * 8 + tg]);
            a[2] = __float_as_uint(S[r0][ka * 8 + tg + 4]);
            a[3] = __float_as_uint(S[r0 + 8][ka * 8 + tg + 4]);
#pragma unroll
            for (int na = 0; na < 4; na++) {
                unsigned b[2] = { Vs[ka * 8 + tg][na * 8 + g],
                                  Vs[ka * 8 + tg + 4][na * 8 + g] };
                mma8(o[na], a, b);
            }
        }

#pragma unroll
        for (int half = 0; half < 2; half++) {
            int row = r0 + half * 8;
            if (row < 49) {
                float s = invs[half];
                float* op = g_ao + (win * 49 + row) * 256 + h * 32;
#pragma unroll
                for (int na = 0; na < 4; na++) {
                    int col = na * 8 + 2 * tg;
                    *(float2*)(op + col) =
                        make_float2(rtf(o[na][half * 2 + 0] * s),
                                    rtf(o[na][half * 2 + 1] * s));
                }
            }
        }
    }
}

// ============================================================
// Proj GEMM: M=50176, N=256, K=256, fused reverse+roll scatter.
// ============================================================
__global__ void __launch_bounds__(256) proj_gemm(
    const float* __restrict__ Bp, float* __restrict__ out)
{
    extern __shared__ float sm[];

    const int tid = threadIdx.x;
    const int m0 = blockIdx.x * 128;
    const int n0 = blockIdx.y * 128;

    const unsigned sbase = (unsigned)__cvta_generic_to_shared(sm);

    int ar[4], ac[4], bk[4], bc[4];
#pragma unroll
    for (int t = 0; t < 4; t++) {
        int id = tid + t * 256;
        ar[t] = id >> 3;  ac[t] = (id & 7) << 2;
        bk[t] = id >> 5;  bc[t] = (id & 31) << 2;
    }

#define ISSUE(STG, K0)                                                        \
    {                                                                         \
        _Pragma("unroll") for (int t = 0; t < 4; t++)                         \
            cpa16(sbase + ((STG) * A_ST + ar[t] * 36 + ac[t]) * 4,            \
                  g_ao + (m0 + ar[t]) * 256 + (K0) + ac[t]);                  \
        _Pragma("unroll") for (int t = 0; t < 4; t++)                         \
            cpa16(sbase + (B_BASE + (STG) * B_ST + bk[t] * 136 + bc[t]) * 4,  \
                  g_wproj + ((K0) + bk[t]) * 256 + n0 + bc[t]);               \
    }

    float acc[4][4][4];
#pragma unroll
    for (int i = 0; i < 4; i++)
#pragma unroll
        for (int j = 0; j < 4; j++)
#pragma unroll
            for (int l = 0; l < 4; l++) acc[i][j][l] = 0.f;

    const int warp = tid >> 5, lane = tid & 31;
    const int g = lane >> 2, tg = lane & 3;
    const int wm = warp >> 2, wn = warp & 3;

    ISSUE(0, 0);  cpa_commit();
    ISSUE(1, 32); cpa_commit();
    cpa_wait<1>();
    __syncthreads();

    for (int it = 0; it < 8; it++) {
        const int stg = it - (it >= 6 ? 6 : (it >= 3 ? 3 : 0));
        const float* As = sm + stg * A_ST;
        const float* Bs = sm + B_BASE + stg * B_ST;

#pragma unroll
        for (int ka = 0; ka < 4; ka++) {
            unsigned a[4][4], bb[4][2];
#pragma unroll
            for (int ma = 0; ma < 4; ma++) {
                int r = wm * 64 + ma * 16 + g;
                a[ma][0] = __float_as_uint(As[r * 36 + ka * 8 + tg]);
                a[ma][1] = __float_as_uint(As[(r + 8) * 36 + ka * 8 + tg]);
                a[ma][2] = __float_as_uint(As[r * 36 + ka * 8 + tg + 4]);
                a[ma][3] = __float_as_uint(As[(r + 8) * 36 + ka * 8 + tg + 4]);
            }
#pragma unroll
            for (int na = 0; na < 4; na++) {
                int c = wn * 32 + na * 8 + g;
                bb[na][0] = __float_as_uint(Bs[(ka * 8 + tg) * 136 + c]);
                bb[na][1] = __float_as_uint(Bs[(ka * 8 + tg + 4) * 136 + c]);
            }
#pragma unroll
            for (int ma = 0; ma < 4; ma++)
#pragma unroll
                for (int na = 0; na < 4; na++) mma8(acc[ma][na], a[ma], bb[na]);
        }

        if (it + 2 < 8) {
            int ns = it + 2; ns -= (ns >= 6 ? 6 : (ns >= 3 ? 3 : 0));
            ISSUE(ns, (it + 2) * 32);
        }
        cpa_commit();
        cpa_wait<1>();
        __syncthreads();
    }
#undef ISSUE

#pragma unroll
    for (int ma = 0; ma < 4; ma++) {
#pragma unroll
        for (int rr = 0; rr < 2; rr++) {
            int r = m0 + wm * 64 + ma * 16 + g + rr * 8;
            int win = r / 49, n = r - win * 49;
            int b = win >> 6, wy = (win >> 3) & 7, wx = win & 7;
            int iy = n / 7, ix = n - iy * 7;
            int y = wy * 7 + iy + 3; if (y >= 56) y -= 56;
            int x = wx * 7 + ix + 3; if (x >= 56) x -= 56;
            int obase = ((b * 56 + y) * 56 + x) * 256;
#pragma unroll
            for (int na = 0; na < 4; na++) {
                int c = n0 + wn * 32 + na * 8 + tg * 2;
                float v0 = acc[ma][na][rr * 2 + 0] + Bp[c];
                float v1 = acc[ma][na][rr * 2 + 1] + Bp[c + 1];
                *(float2*)(out + obase + c) = make_float2(v0, v1);
            }
        }
    }
}

// ============================================================
extern "C" void kernel_launch(void* const* d_in, const int* in_sizes, int n_in,
                              void* d_out, int out_size)
{
    const float* query  = (const float*)d_in[0];
    const float* w_qkv  = (const float*)d_in[1];
    const float* b_qkv  = (const float*)d_in[2];
    const float* w_proj = (const float*)d_in[3];
    const float* b_proj = (const float*)d_in[4];
    const float* rbt    = (const float*)d_in[5];
    float* out = (float*)d_out;

    static int attr_done = 0;
    if (!attr_done) {
        cudaFuncSetAttribute(qkv_gemm,
            cudaFuncAttributeMaxDynamicSharedMemorySize, SMEM_BYTES);
        cudaFuncSetAttribute(proj_gemm,
            cudaFuncAttributeMaxDynamicSharedMemorySize, SMEM_BYTES);
        attr_done = 1;
    }

    round_pre<<<12800, 256>>>((const float4*)query, (const float4*)w_qkv,
                              (const float4*)w_proj);

    dim3 g1(392, 6);
    qkv_gemm<<<g1, 256, SMEM_BYTES>>>(b_qkv);

    attn_kernel<<<8192, 128>>>(rbt);

    dim3 g3(392, 2);
    proj_gemm<<<g3, 256, SMEM_BYTES>>>(b_proj, out);
}

// round 5
// speedup vs baseline: 1.8583x; 1.5002x over previous
#include <cuda_runtime.h>

#define NHEAD  8
#define HDIM   32
#define CD     256
#define NTOK   49
#define BWIN   1024
#define MROWS  50176
#define NW1    196608             // 256*768
#define NW2    65536              // 256*256

__device__ float g_q[BWIN * NHEAD * NTOK * HDIM];
__device__ float g_k[BWIN * NHEAD * NTOK * HDIM];
__device__ float g_v[BWIN * NHEAD * NTOK * HDIM];
__device__ float g_ao[MROWS * CD];
__device__ float g_wqkv[NW1];
__device__ float g_wproj[NW2];

__device__ __forceinline__ unsigned f2tf(float f) {
    unsigned u;
    asm("cvt.rna.tf32.f32 %0, %1;" : "=r"(u) : "f"(f));
    return u;
}
__device__ __forceinline__ float rtf(float f) { return __uint_as_float(f2tf(f)); }

__device__ __forceinline__ void mma8(float* c, const unsigned* a, const unsigned* b) {
    asm volatile(
        "mma.sync.aligned.m16n8k8.row.col.f32.tf32.tf32.f32 "
        "{%0,%1,%2,%3},{%4,%5,%6,%7},{%8,%9},{%0,%1,%2,%3};"
        : "+f"(c[0]), "+f"(c[1]), "+f"(c[2]), "+f"(c[3])
        : "r"(a[0]), "r"(a[1]), "r"(a[2]), "r"(a[3]), "r"(b[0]), "r"(b[1]));
}

__device__ __forceinline__ void cpa16(unsigned dst, const void* src) {
    asm volatile("cp.async.cg.shared.global [%0], [%1], 16;" :: "r"(dst), "l"(src));
}
__device__ __forceinline__ void cpa_commit() {
    asm volatile("cp.async.commit_group;");
}
template <int N>
__device__ __forceinline__ void cpa_wait() {
    asm volatile("cp.async.wait_group %0;" :: "n"(N));
}

// ============================================================
// Pre-pass: round ONLY the weights to TF32 (1 MB total).
// Activations feed the MMAs raw (hardware truncation).
// ============================================================
__global__ void __launch_bounds__(256) round_w(
    const float4* __restrict__ w1, const float4* __restrict__ w2)
{
    int i = blockIdx.x * 256 + threadIdx.x;
    const int NW14 = NW1 / 4;
    float4 v; float4* dst;
    if (i < NW14) { v = w1[i];         dst = (float4*)g_wqkv + i; }
    else          { v = w2[i - NW14];  dst = (float4*)g_wproj + (i - NW14); }
    *dst = make_float4(rtf(v.x), rtf(v.y), rtf(v.z), rtf(v.w));
}

// ============================================================
// GEMM tiles: block 128x128, 8 warps (2m x 4n), warp 64x32,
// K-slice 32, 3-stage cp.async pipeline.
// ============================================================
#define A_ST 4608
#define B_ST 4352
#define B_BASE 13824
#define SMEM_BYTES 107520

__global__ void __launch_bounds__(256) qkv_gemm(
    const float* __restrict__ Q, const float* __restrict__ Bq)
{
    extern __shared__ float sm[];
    __shared__ int rsrc[128];

    const int tid = threadIdx.x;
    const int m0 = blockIdx.x * 128;
    const int n0 = blockIdx.y * 128;

    if (tid < 128) {
        int m = m0 + tid;
        int win = m / 49, n = m - win * 49;
        int b = win >> 6, wy = (win >> 3) & 7, wx = win & 7;
        int iy = n / 7, ix = n - iy * 7;
        int y = wy * 7 + iy + 3; if (y >= 56) y -= 56;
        int x = wx * 7 + ix + 3; if (x >= 56) x -= 56;
        rsrc[tid] = ((b * 56 + y) * 56 + x) * 256;
    }
    __syncthreads();

    const unsigned sbase = (unsigned)__cvta_generic_to_shared(sm);

    int ar[4], ac[4], bk[4], bc[4];
#pragma unroll
    for (int t = 0; t < 4; t++) {
        int id = tid + t * 256;
        ar[t] = id >> 3;  ac[t] = (id & 7) << 2;
        bk[t] = id >> 5;  bc[t] = (id & 31) << 2;
    }

#define ISSUE(STG, K0)                                                        \
    {                                                                         \
        _Pragma("unroll") for (int t = 0; t < 4; t++)                         \
            cpa16(sbase + ((STG) * A_ST + ar[t] * 36 + ac[t]) * 4,            \
                  Q + rsrc[ar[t]] + (K0) + ac[t]);                            \
        _Pragma("unroll") for (int t = 0; t < 4; t++)                         \
            cpa16(sbase + (B_BASE + (STG) * B_ST + bk[t] * 136 + bc[t]) * 4,  \
                  g_wqkv + ((K0) + bk[t]) * 768 + n0 + bc[t]);                \
    }

    float acc[4][4][4];
#pragma unroll
    for (int i = 0; i < 4; i++)
#pragma unroll
        for (int j = 0; j < 4; j++)
#pragma unroll
            for (int l = 0; l < 4; l++) acc[i][j][l] = 0.f;

    const int warp = tid >> 5, lane = tid & 31;
    const int g = lane >> 2, tg = lane & 3;
    const int wm = warp >> 2, wn = warp & 3;

    ISSUE(0, 0);  cpa_commit();
    ISSUE(1, 32); cpa_commit();
    cpa_wait<1>();
    __syncthreads();

    for (int it = 0; it < 8; it++) {
        const int stg = it - (it >= 6 ? 6 : (it >= 3 ? 3 : 0));
        const float* As = sm + stg * A_ST;
        const float* Bs = sm + B_BASE + stg * B_ST;

#pragma unroll
        for (int ka = 0; ka < 4; ka++) {
            unsigned a[4][4], bb[4][2];
#pragma unroll
            for (int ma = 0; ma < 4; ma++) {
                int r = wm * 64 + ma * 16 + g;
                a[ma][0] = __float_as_uint(As[r * 36 + ka * 8 + tg]);
                a[ma][1] = __float_as_uint(As[(r + 8) * 36 + ka * 8 + tg]);
                a[ma][2] = __float_as_uint(As[r * 36 + ka * 8 + tg + 4]);
                a[ma][3] = __float_as_uint(As[(r + 8) * 36 + ka * 8 + tg + 4]);
            }
#pragma unroll
            for (int na = 0; na < 4; na++) {
                int c = wn * 32 + na * 8 + g;
                bb[na][0] = __float_as_uint(Bs[(ka * 8 + tg) * 136 + c]);
                bb[na][1] = __float_as_uint(Bs[(ka * 8 + tg + 4) * 136 + c]);
            }
#pragma unroll
            for (int ma = 0; ma < 4; ma++)
#pragma unroll
                for (int na = 0; na < 4; na++) mma8(acc[ma][na], a[ma], bb[na]);
        }

        if (it + 2 < 8) {
            int ns = it + 2; ns -= (ns >= 6 ? 6 : (ns >= 3 ? 3 : 0));
            ISSUE(ns, (it + 2) * 32);
        }
        cpa_commit();
        cpa_wait<1>();
        __syncthreads();
    }
#undef ISSUE

    const float scale = 0.17677669529663687f;
#pragma unroll
    for (int ma = 0; ma < 4; ma++) {
#pragma unroll
        for (int rr = 0; rr < 2; rr++) {
            int r = m0 + wm * 64 + ma * 16 + g + rr * 8;
            int win = r / 49, n = r - win * 49;
#pragma unroll
            for (int na = 0; na < 4; na++) {
                int c = n0 + wn * 32 + na * 8 + tg * 2;
                float v0 = acc[ma][na][rr * 2 + 0] + Bq[c];
                float v1 = acc[ma][na][rr * 2 + 1] + Bq[c + 1];
                int part = c >> 8;
                if (part == 0) { v0 *= scale; v1 *= scale; }
                int hh = (c >> 5) & 7, d = c & 31;
                float* dst = (part == 0) ? g_q : ((part == 1) ? g_k : g_v);
                *(float2*)(dst + (((win << 3) + hh) * 49 + n) * 32 + d) =
                    make_float2(rtf(v0), rtf(v1));
            }
        }
    }
}

// ============================================================
// Attention: block = (window, head), 128 threads.
// All Q/K/V loads are coalesced uint4 copies (K kept in natural
// [token][d] layout; B fragment indexed directly). Fused
// bias+mask+exp+rowsum epilogue; single block-wide sync.
// ============================================================
__global__ void __launch_bounds__(128) attn_kernel(const float* __restrict__ rbt)
{
    const int bx = blockIdx.x;
    const int win = bx >> 3, h = bx & 7;

    __shared__ unsigned As[64][36];      // Q  (rows 49-63 unused garbage)
    __shared__ unsigned Ks[56][36];      // K natural layout, rows 49-55 zero
    __shared__ unsigned Vs[56][36];      // V natural layout, rows 49-55 zero
    __shared__ float    S[64][57];
    __shared__ float    biasH[169];
    __shared__ int      cnt[49];

    const int tid = threadIdx.x;
    const int warp = tid >> 5, lane = tid & 31;
    const int g = lane >> 2, tg = lane & 3;

    const int base = ((win * 8 + h) * 49) * 32;
    const float* qp = g_q + base;
    const float* kp = g_k + base;
    const float* vp = g_v + base;

    for (int i = tid; i < 392; i += 128) {
        int r = i >> 3, c = (i & 7) << 2;
        *(uint4*)&As[r][c] = ((const uint4*)qp)[i];
        *(uint4*)&Ks[r][c] = ((const uint4*)kp)[i];
        *(uint4*)&Vs[r][c] = ((const uint4*)vp)[i];
    }
    if (tid < 112) {                                  // zero pad rows 49-55
        int a = tid >> 3, c = (tid & 7) << 2;
        uint4 z = make_uint4(0u, 0u, 0u, 0u);
        if (a < 7) *(uint4*)&Ks[49 + a][c] = z;
        else       *(uint4*)&Vs[42 + a][c] = z;       // 49 + (a-7)
    }
    for (int i = tid; i < 169; i += 128) biasH[i] = rbt[i * 8 + h];
    if (tid < 49) {
        int iy = tid / 7, ix = tid - iy * 7;
        int wy = (win >> 3) & 7, wx = win & 7;
        int y = wy * 7 + iy, x = wx * 7 + ix;
        int ry = y < 49 ? 0 : (y < 53 ? 1 : 2);
        int rx = x < 49 ? 0 : (x < 53 ? 1 : 2);
        cnt[tid] = ry * 3 + rx;
    }
    __syncthreads();

    // ---- S = Q K^T with fused bias+mask+exp+rowsum ----
    const int r0 = warp * 16 + g;
    float invs[2];

    // per-thread column coords (col = na*8 + 2*tg + e), hoisted
    int cjy[7][2], cjx[7][2];
#pragma unroll
    for (int na = 0; na < 7; na++)
#pragma unroll
        for (int e = 0; e < 2; e++) {
            int col = na * 8 + 2 * tg + e;
            cjy[na][e] = (col < 49) ? col / 7 : -1;
            cjx[na][e] = col - cjy[na][e] * 7;
        }

    {
        float acc[7][4];
#pragma unroll
        for (int na = 0; na < 7; na++)
#pragma unroll
            for (int l = 0; l < 4; l++) acc[na][l] = 0.f;

#pragma unroll
        for (int ka = 0; ka < 4; ka++) {
            unsigned a[4];
            a[0] = As[r0][ka * 8 + tg];
            a[1] = As[r0 + 8][ka * 8 + tg];
            a[2] = As[r0][ka * 8 + tg + 4];
            a[3] = As[r0 + 8][ka * 8 + tg + 4];
#pragma unroll
            for (int na = 0; na < 7; na++) {
                unsigned b[2] = { Ks[na * 8 + g][ka * 8 + tg],
                                  Ks[na * 8 + g][ka * 8 + tg + 4] };
                mma8(acc[na], a, b);
            }
        }

#pragma unroll
        for (int half = 0; half < 2; half++) {
            int row = r0 + half * 8;
            bool rok = row < 49;
            int iy = 0, ix = 0, ci = 0;
            if (rok) { iy = row / 7; ix = row - iy * 7; ci = cnt[row]; }
            float esum = 0.f;
#pragma unroll
            for (int na = 0; na < 7; na++) {
#pragma unroll
                for (int e = 0; e < 2; e++) {
                    int col = na * 8 + 2 * tg + e;
                    float ev = 0.f;
                    if (rok && cjy[na][e] >= 0) {
                        float v = acc[na][half * 2 + e]
                                + biasH[(iy - cjy[na][e] + 6) * 13
                                        + (ix - cjx[na][e] + 6)];
                        if (cnt[col] != ci) v -= 100.f;
                        ev = __expf(v);
                    }
                    S[row][col] = __uint_as_float(f2tf(ev));
                    esum += ev;
                }
            }
            esum += __shfl_xor_sync(0xffffffffu, esum, 1);
            esum += __shfl_xor_sync(0xffffffffu, esum, 2);
            invs[half] = 1.f / esum;
        }
    }
    __syncwarp();

    // ---- O = P V ----
    {
        float o[4][4];
#pragma unroll
        for (int na = 0; na < 4; na++)
#pragma unroll
            for (int l = 0; l < 4; l++) o[na][l] = 0.f;

#pragma unroll
        for (int ka = 0; ka < 7; ka++) {
            unsigned a[4];
            a[0] = __float_as_uint(S[r0][ka * 8 + tg]);
            a[1] = __float_as_uint(S[r0 + 8][ka * 8 + tg]);
            a[2] = __float_as_uint(S[r0][ka * 8 + tg + 4]);
            a[3] = __float_as_uint(S[r0 + 8][ka * 8 + tg + 4]);
#pragma unroll
            for (int na = 0; na < 4; na++) {
                unsigned b[2] = { Vs[ka * 8 + tg][na * 8 + g],
                                  Vs[ka * 8 + tg + 4][na * 8 + g] };
                mma8(o[na], a, b);
            }
        }

#pragma unroll
        for (int half = 0; half < 2; half++) {
            int row = r0 + half * 8;
            if (row < 49) {
                float s = invs[half];
                float* op = g_ao + (win * 49 + row) * 256 + h * 32;
#pragma unroll
                for (int na = 0; na < 4; na++) {
                    int col = na * 8 + 2 * tg;
                    *(float2*)(op + col) =
                        make_float2(rtf(o[na][half * 2 + 0] * s),
                                    rtf(o[na][half * 2 + 1] * s));
                }
            }
        }
    }
}

// ============================================================
// Proj GEMM: M=50176, N=256, K=256, fused reverse+roll scatter.
// ============================================================
__global__ void __launch_bounds__(256) proj_gemm(
    const float* __restrict__ Bp, float* __restrict__ out)
{
    extern __shared__ float sm[];

    const int tid = threadIdx.x;
    const int m0 = blockIdx.x * 128;
    const int n0 = blockIdx.y * 128;

    const unsigned sbase = (unsigned)__cvta_generic_to_shared(sm);

    int ar[4], ac[4], bk[4], bc[4];
#pragma unroll
    for (int t = 0; t < 4; t++) {
        int id = tid + t * 256;
        ar[t] = id >> 3;  ac[t] = (id & 7) << 2;
        bk[t] = id >> 5;  bc[t] = (id & 31) << 2;
    }

#define ISSUE(STG, K0)                                                        \
    {                                                                         \
        _Pragma("unroll") for (int t = 0; t < 4; t++)                         \
            cpa16(sbase + ((STG) * A_ST + ar[t] * 36 + ac[t]) * 4,            \
                  g_ao + (m0 + ar[t]) * 256 + (K0) + ac[t]);                  \
        _Pragma("unroll") for (int t = 0; t < 4; t++)                         \
            cpa16(sbase + (B_BASE + (STG) * B_ST + bk[t] * 136 + bc[t]) * 4,  \
                  g_wproj + ((K0) + bk[t]) * 256 + n0 + bc[t]);               \
    }

    float acc[4][4][4];
#pragma unroll
    for (int i = 0; i < 4; i++)
#pragma unroll
        for (int j = 0; j < 4; j++)
#pragma unroll
            for (int l = 0; l < 4; l++) acc[i][j][l] = 0.f;

    const int warp = tid >> 5, lane = tid & 31;
    const int g = lane >> 2, tg = lane & 3;
    const int wm = warp >> 2, wn = warp & 3;

    ISSUE(0, 0);  cpa_commit();
    ISSUE(1, 32); cpa_commit();
    cpa_wait<1>();
    __syncthreads();

    for (int it = 0; it < 8; it++) {
        const int stg = it - (it >= 6 ? 6 : (it >= 3 ? 3 : 0));
        const float* As = sm + stg * A_ST;
        const float* Bs = sm + B_BASE + stg * B_ST;

#pragma unroll
        for (int ka = 0; ka < 4; ka++) {
            unsigned a[4][4], bb[4][2];
#pragma unroll
            for (int ma = 0; ma < 4; ma++) {
                int r = wm * 64 + ma * 16 + g;
                a[ma][0] = __float_as_uint(As[r * 36 + ka * 8 + tg]);
                a[ma][1] = __float_as_uint(As[(r + 8) * 36 + ka * 8 + tg]);
                a[ma][2] = __float_as_uint(As[r * 36 + ka * 8 + tg + 4]);
                a[ma][3] = __float_as_uint(As[(r + 8) * 36 + ka * 8 + tg + 4]);
            }
#pragma unroll
            for (int na = 0; na < 4; na++) {
                int c = wn * 32 + na * 8 + g;
                bb[na][0] = __float_as_uint(Bs[(ka * 8 + tg) * 136 + c]);
                bb[na][1] = __float_as_uint(Bs[(ka * 8 + tg + 4) * 136 + c]);
            }
#pragma unroll
            for (int ma = 0; ma < 4; ma++)
#pragma unroll
                for (int na = 0; na < 4; na++) mma8(acc[ma][na], a[ma], bb[na]);
        }

        if (it + 2 < 8) {
            int ns = it + 2; ns -= (ns >= 6 ? 6 : (ns >= 3 ? 3 : 0));
            ISSUE(ns, (it + 2) * 32);
        }
        cpa_commit();
        cpa_wait<1>();
        __syncthreads();
    }
#undef ISSUE

#pragma unroll
    for (int ma = 0; ma < 4; ma++) {
#pragma unroll
        for (int rr = 0; rr < 2; rr++) {
            int r = m0 + wm * 64 + ma * 16 + g + rr * 8;
            int win = r / 49, n = r - win * 49;
            int b = win >> 6, wy = (win >> 3) & 7, wx = win & 7;
            int iy = n / 7, ix = n - iy * 7;
            int y = wy * 7 + iy + 3; if (y >= 56) y -= 56;
            int x = wx * 7 + ix + 3; if (x >= 56) x -= 56;
            int obase = ((b * 56 + y) * 56 + x) * 256;
#pragma unroll
            for (int na = 0; na < 4; na++) {
                int c = n0 + wn * 32 + na * 8 + tg * 2;
                float v0 = acc[ma][na][rr * 2 + 0] + Bp[c];
                float v1 = acc[ma][na][rr * 2 + 1] + Bp[c + 1];
                *(float2*)(out + obase + c) = make_float2(v0, v1);
            }
        }
    }
}

// ============================================================
extern "C" void kernel_launch(void* const* d_in, const int* in_sizes, int n_in,
                              void* d_out, int out_size)
{
    const float* query  = (const float*)d_in[0];
    const float* w_qkv  = (const float*)d_in[1];
    const float* b_qkv  = (const float*)d_in[2];
    const float* w_proj = (const float*)d_in[3];
    const float* b_proj = (const float*)d_in[4];
    const float* rbt    = (const float*)d_in[5];
    float* out = (float*)d_out;

    static int attr_done = 0;
    if (!attr_done) {
        cudaFuncSetAttribute(qkv_gemm,
            cudaFuncAttributeMaxDynamicSharedMemorySize, SMEM_BYTES);
        cudaFuncSetAttribute(proj_gemm,
            cudaFuncAttributeMaxDynamicSharedMemorySize, SMEM_BYTES);
        attr_done = 1;
    }

    round_w<<<256, 256>>>((const float4*)w_qkv, (const float4*)w_proj);

    dim3 g1(392, 6);
    qkv_gemm<<<g1, 256, SMEM_BYTES>>>(query, b_qkv);

    attn_kernel<<<8192, 128>>>(rbt);

    dim3 g3(392, 2);
    proj_gemm<<<g3, 256, SMEM_BYTES>>>(b_proj, out);
}